// round 17
// baseline (speedup 1.0000x reference)
#include <cuda_runtime.h>
#include <cuda_fp16.h>

#define S_LEN 128
#define NH 8
#define INF9 1.0e9f
#define LOG2E 1.4426950408889634f

// Weight fragments in fp16 B-frag layout (uint = half2), prepped per launch.
__device__ unsigned g_Wfu[3 * 8 * 1024];   // [z][h][kg4][nf4][lane32][p2]
__device__ unsigned g_Wofu[8 * 1024];      // flat [kgAbs16][nf8][lane32][p2]
// bias*log2e in C-frag-major fp16: [h8][qt16][kt16][lane32][reg4 half2]
__device__ unsigned g_B16[262144];
// X in fp16 A-frag layout: [rtAbs 2048][kg4][lane32][reg4]
__device__ unsigned g_Xqf[2048 * 512];
__device__ unsigned g_Xkf[2048 * 512];
// Normalized attention output, fp16 A-frags: [rtAbs 2048][kgAbs16][lane32][reg4]
__device__ unsigned g_Of[2048 * 2048];

__device__ __forceinline__ unsigned pk(float a, float b) {
  __half2 h = __floats2half2_rn(a, b);
  return *(unsigned*)&h;
}
__device__ __forceinline__ float2 h22f2(unsigned u) {
  __half2 h = *(__half2*)&u;
  return __half22float2(h);
}

__device__ __forceinline__ void mma16(float4& c, unsigned a0, unsigned a1,
                                      unsigned a2, unsigned a3, unsigned b0,
                                      unsigned b1) {
  asm volatile(
      "mma.sync.aligned.m16n8k16.row.col.f32.f16.f16.f32 "
      "{%0,%1,%2,%3}, {%4,%5,%6,%7}, {%8,%9}, {%0,%1,%2,%3};"
      : "+f"(c.x), "+f"(c.y), "+f"(c.z), "+f"(c.w)
      : "r"(a0), "r"(a1), "r"(a2), "r"(a3), "r"(b0), "r"(b1));
}

// ---------------------------------------------------------------------------
// Prep (merged): blocks [0,1152) do weight/bias frag prep; blocks [1152,3200)
// stage X into fp16 A-frag layout.
// ---------------------------------------------------------------------------
__global__ void prep_kernel(const float* __restrict__ wq,
                            const float* __restrict__ wk,
                            const float* __restrict__ wv,
                            const float* __restrict__ wo,
                            const float* __restrict__ bias,
                            const float* __restrict__ xq,
                            const float* __restrict__ xkv) {
  const float scale = 0.17677669529663687f * LOG2E;
  if (blockIdx.x < 1152) {
    int id = blockIdx.x * 256 + threadIdx.x;
    if (id < 24576) {
      int p = id & 1, lane = (id >> 1) & 31, nf = (id >> 6) & 3,
          kg = (id >> 8) & 3, h = (id >> 10) & 7, z = id >> 13;
      int r4 = lane >> 2, c4 = lane & 3;
      const float* w = (z == 0) ? wq : (z == 1) ? wk : wv;
      int k0 = kg * 16 + 2 * c4 + 8 * p;
      int col = h * 32 + nf * 8 + r4;
      float v0 = w[k0 * 256 + col], v1 = w[(k0 + 1) * 256 + col];
      if (z == 0) { v0 *= scale; v1 *= scale; }
      g_Wfu[id] = pk(v0, v1);
    } else if (id < 32768) {
      int id2 = id - 24576;
      int p = id2 & 1, lane = (id2 >> 1) & 31, nf = (id2 >> 6) & 7,
          kg = (id2 >> 9) & 1, h = id2 >> 10;
      int r4 = lane >> 2, c4 = lane & 3;
      int k0 = kg * 16 + 2 * c4 + 8 * p;
      int col = nf * 8 + r4;
      g_Wofu[id2] = pk(wo[(h * 32 + k0) * 64 + col],
                       wo[(h * 32 + k0 + 1) * 64 + col]);
    } else {
      int id2 = id - 32768;  // [0, 262144) — one half2 of bias frag layout
      int reg = id2 & 3, lane = (id2 >> 2) & 31, kt = (id2 >> 7) & 15,
          qt = (id2 >> 11) & 15, h = id2 >> 15;
      int r4 = lane >> 2, c4 = lane & 3;
      int row = qt * 16 + r4 + 8 * (reg & 1);
      int col = kt * 16 + 2 * c4 + 8 * (reg >> 1);
      const float* bp = bias + ((size_t)h * 256 + row) * 256 + col;
      g_B16[id2] = pk(bp[0] * LOG2E, bp[1] * LOG2E);
    }
  } else {
    int id2 = (blockIdx.x - 1152) * 256 + threadIdx.x;  // [0, 524288)
    int row = id2 >> 4, k0 = (id2 & 15) * 4;
    float4 a = *(const float4*)(xq + (size_t)row * 64 + k0);
    float4 b = *(const float4*)(xkv + (size_t)row * 64 + k0);
    int rt = row >> 4, kg = k0 >> 4;
    int rr = row & 15, r4s = rr & 7, eR = rr >> 3;
    int pi0 = (k0 & 15) >> 1;
    int c4a = pi0 & 3, hi = pi0 >> 2;
    int reg = eR + 2 * hi;
    int base = (((rt * 4 + kg) * 32 + r4s * 4 + c4a) * 4) + reg;
    g_Xqf[base] = pk(a.x, a.y);
    g_Xqf[base + 4] = pk(a.z, a.w);
    g_Xkf[base] = pk(b.x, b.y);
    g_Xkf[base + 4] = pk(b.z, b.w);
  }
}

// ---------------------------------------------------------------------------
// Attention kernel: grid (s, h) = 1024 blocks, 256 threads, 2 blocks/SM.
// Warp owns 32 q rows (mt=2) and 32 kv rows. Projects Q/K/V for its head,
// runs attention, writes normalized O as fp16 A-frags to g_Of.
// Bias read as one LDG.128 per (kt, mt) from frag-major layout.
// ---------------------------------------------------------------------------
#define AWS_OFF 0
#define AKS_OFF 3072
#define AVS_OFF 7168
#define AMS_OFF 11264
#define ATTN_SMEM ((11264 + 256) * 4)
#define ONE2 0x3C003C00u

__global__ __launch_bounds__(256, 2) void attn_kernel(
    const float* __restrict__ mask) {
  extern __shared__ unsigned smu[];
  float* ms = (float*)(smu + AMS_OFF);

  const int tid = threadIdx.x;
  const int s = blockIdx.x, h = blockIdx.y;

  // stage this head's Wq/Wk/Wv frags (768 uint4)
  {
    uint4* dst = (uint4*)(smu + AWS_OFF);
#pragma unroll
    for (int i = tid; i < 768; i += 256) {
      int z = i >> 8, wi = i & 255;
      dst[i] = ((const uint4*)g_Wfu)[(z * 8 + h) * 256 + wi];
    }
  }
  ms[tid] = ((mask[s * 256 + tid] - 1.0f) * INF9 - 4.0f) * LOG2E;
  __syncthreads();

  const int w = tid >> 5, lane = tid & 31;
  const int r4 = lane >> 2, c4 = lane & 3;
  const int rtB = s * 16 + w * 2;  // this warp's abs row-tiles (q and kv)

  const uint2* Ws2 = (const uint2*)(smu + AWS_OFF);
  const uint2* Ks2 = (const uint2*)(smu + AKS_OFF);
  const uint2* Vs2 = (const uint2*)(smu + AVS_OFF);
  const uint4* Xqf4 = (const uint4*)g_Xqf;
  const uint4* Xkf4 = (const uint4*)g_Xkf;

  // ---- Q = Xq @ Wq_h -> qa A-frags ----
  uint4 qa[2][2];
  {
    float4 acc[2][4];
#pragma unroll
    for (int i = 0; i < 2; i++)
#pragma unroll
      for (int j = 0; j < 4; j++) acc[i][j] = make_float4(0.f, 0.f, 0.f, 0.f);
#pragma unroll
    for (int kg = 0; kg < 4; kg++) {
      uint4 A0 = Xqf4[((rtB + 0) * 4 + kg) * 32 + lane];
      uint4 A1 = Xqf4[((rtB + 1) * 4 + kg) * 32 + lane];
#pragma unroll
      for (int nf = 0; nf < 4; nf++) {
        uint2 B = Ws2[(kg * 4 + nf) * 32 + lane];
        mma16(acc[0][nf], A0.x, A0.y, A0.z, A0.w, B.x, B.y);
        mma16(acc[1][nf], A1.x, A1.y, A1.z, A1.w, B.x, B.y);
      }
    }
#pragma unroll
    for (int mt = 0; mt < 2; mt++)
#pragma unroll
      for (int kg = 0; kg < 2; kg++)
        qa[mt][kg] = make_uint4(pk(acc[mt][2 * kg].x, acc[mt][2 * kg].y),
                                pk(acc[mt][2 * kg].z, acc[mt][2 * kg].w),
                                pk(acc[mt][2 * kg + 1].x, acc[mt][2 * kg + 1].y),
                                pk(acc[mt][2 * kg + 1].z, acc[mt][2 * kg + 1].w));
  }

  // ---- K = Xkv @ Wk_h -> Ks scatter ----
  {
    float4 acc[2][4];
#pragma unroll
    for (int i = 0; i < 2; i++)
#pragma unroll
      for (int j = 0; j < 4; j++) acc[i][j] = make_float4(0.f, 0.f, 0.f, 0.f);
#pragma unroll
    for (int kg = 0; kg < 4; kg++) {
      uint4 A0 = Xkf4[((rtB + 0) * 4 + kg) * 32 + lane];
      uint4 A1 = Xkf4[((rtB + 1) * 4 + kg) * 32 + lane];
#pragma unroll
      for (int nf = 0; nf < 4; nf++) {
        uint2 B = Ws2[512 + (kg * 4 + nf) * 32 + lane];
        mma16(acc[0][nf], A0.x, A0.y, A0.z, A0.w, B.x, B.y);
        mma16(acc[1][nf], A1.x, A1.y, A1.z, A1.w, B.x, B.y);
      }
    }
#pragma unroll
    for (int mt = 0; mt < 2; mt++) {
      int kt = w * 2 + mt;  // local kv tile
#pragma unroll
      for (int nf = 0; nf < 4; nf++) {
        int kgd = nf >> 1, pp = nf & 1;
        smu[AKS_OFF + (((kt * 2 + kgd) * 2 + 0) * 32 + lane) * 2 + pp] =
            pk(acc[mt][nf].x, acc[mt][nf].y);
        smu[AKS_OFF + (((kt * 2 + kgd) * 2 + 1) * 32 + lane) * 2 + pp] =
            pk(acc[mt][nf].z, acc[mt][nf].w);
      }
    }
  }

  // ---- V = Xkv @ Wv_h -> Vs scatter ----
  {
    float4 acc[2][4];
#pragma unroll
    for (int i = 0; i < 2; i++)
#pragma unroll
      for (int j = 0; j < 4; j++) acc[i][j] = make_float4(0.f, 0.f, 0.f, 0.f);
#pragma unroll
    for (int kg = 0; kg < 4; kg++) {
      uint4 A0 = Xkf4[((rtB + 0) * 4 + kg) * 32 + lane];
      uint4 A1 = Xkf4[((rtB + 1) * 4 + kg) * 32 + lane];
#pragma unroll
      for (int nf = 0; nf < 4; nf++) {
        uint2 B = Ws2[1024 + (kg * 4 + nf) * 32 + lane];
        mma16(acc[0][nf], A0.x, A0.y, A0.z, A0.w, B.x, B.y);
        mma16(acc[1][nf], A1.x, A1.y, A1.z, A1.w, B.x, B.y);
      }
    }
    __half* Vh = (__half*)(smu + AVS_OFF);
    int e = r4 & 1, cp = r4 >> 1;
#pragma unroll
    for (int mt = 0; mt < 2; mt++) {
      int kt = w * 2 + mt;
#pragma unroll
      for (int nf = 0; nf < 4; nf++) {
        int b0 = (((kt * 4 + nf) * 32 + (2 * c4) * 4 + cp) * 4) + e;
        int b1 = b0 + 16;
        Vh[b0] = __float2half_rn(acc[mt][nf].x);
        Vh[b0 + 2] = __float2half_rn(acc[mt][nf].z);
        Vh[b1] = __float2half_rn(acc[mt][nf].y);
        Vh[b1 + 2] = __float2half_rn(acc[mt][nf].w);
      }
    }
  }
  __syncthreads();  // Ks/Vs ready

  // ---- attention ----
  float4 o[2][4];
#pragma unroll
  for (int mt = 0; mt < 2; mt++)
#pragma unroll
    for (int nf = 0; nf < 4; nf++) o[mt][nf] = make_float4(0.f, 0.f, 0.f, 0.f);
  float4 lpq[2] = {make_float4(0.f, 0.f, 0.f, 0.f),
                   make_float4(0.f, 0.f, 0.f, 0.f)};

  // frag-major bias: one uint4 per (kt, mt)
  const uint4* Bf4 = (const uint4*)g_B16;
  size_t bbase[2];
#pragma unroll
  for (int mt = 0; mt < 2; mt++)
    bbase[mt] = ((size_t)(h * 16 + w * 2 + mt) * 16) * 32 + lane;

  uint4 cbuf[2][2];  // [slot][mt]
#pragma unroll
  for (int sl = 0; sl < 2; sl++)
#pragma unroll
    for (int mt = 0; mt < 2; mt++) cbuf[sl][mt] = Bf4[bbase[mt] + sl * 32];

#pragma unroll 2
  for (int kt = 0; kt < 16; kt++) {
    const int kv0 = kt * 16;
    const int sl = kt & 1;

    float2 m0 = *(const float2*)(ms + kv0 + 2 * c4);
    float2 m1 = *(const float2*)(ms + kv0 + 8 + 2 * c4);

    float4 Sf[2][2];
#pragma unroll
    for (int mt = 0; mt < 2; mt++) {
      float2 c00 = h22f2(cbuf[sl][mt].x);
      float2 c01 = h22f2(cbuf[sl][mt].y);
      float2 c10 = h22f2(cbuf[sl][mt].z);
      float2 c11 = h22f2(cbuf[sl][mt].w);
      Sf[mt][0] = make_float4(c00.x + m0.x, c00.y + m0.y,
                              c01.x + m0.x, c01.y + m0.y);
      Sf[mt][1] = make_float4(c10.x + m1.x, c10.y + m1.y,
                              c11.x + m1.x, c11.y + m1.y);
    }

    if (kt < 14) {
#pragma unroll
      for (int mt = 0; mt < 2; mt++)
        cbuf[sl][mt] = Bf4[bbase[mt] + (kt + 2) * 32];
    }

#pragma unroll
    for (int kg = 0; kg < 2; kg++) {
      uint2 Kb0 = Ks2[((kt * 2 + kg) * 2 + 0) * 32 + lane];
      uint2 Kb1 = Ks2[((kt * 2 + kg) * 2 + 1) * 32 + lane];
#pragma unroll
      for (int mt = 0; mt < 2; mt++) {
        mma16(Sf[mt][0], qa[mt][kg].x, qa[mt][kg].y, qa[mt][kg].z,
              qa[mt][kg].w, Kb0.x, Kb0.y);
        mma16(Sf[mt][1], qa[mt][kg].x, qa[mt][kg].y, qa[mt][kg].z,
              qa[mt][kg].w, Kb1.x, Kb1.y);
      }
    }

    uint2 Vb[4];
#pragma unroll
    for (int nf = 0; nf < 4; nf++) Vb[nf] = Vs2[(kt * 4 + nf) * 32 + lane];

#pragma unroll
    for (int mt = 0; mt < 2; mt++) {
      float p00 = exp2f(Sf[mt][0].x), p01 = exp2f(Sf[mt][0].y);
      float p02 = exp2f(Sf[mt][0].z), p03 = exp2f(Sf[mt][0].w);
      float p10 = exp2f(Sf[mt][1].x), p11 = exp2f(Sf[mt][1].y);
      float p12 = exp2f(Sf[mt][1].z), p13 = exp2f(Sf[mt][1].w);
      unsigned pa0 = pk(p00, p01), pa1 = pk(p02, p03);
      unsigned pa2 = pk(p10, p11), pa3 = pk(p12, p13);
      mma16(lpq[mt], pa0, pa1, pa2, pa3, ONE2, ONE2);
#pragma unroll
      for (int nf = 0; nf < 4; nf++)
        mma16(o[mt][nf], pa0, pa1, pa2, pa3, Vb[nf].x, Vb[nf].y);
    }
  }

  // ---- normalize, pack to A-frags, write g_Of ----
  uint4* Of4 = (uint4*)g_Of;
#pragma unroll
  for (int mt = 0; mt < 2; mt++) {
    float inv0 = 1.0f / lpq[mt].x;
    float inv8 = 1.0f / lpq[mt].z;
    int rtA = rtB + mt;
#pragma unroll
    for (int kg = 0; kg < 2; kg++) {
      uint4 val = make_uint4(
          pk(o[mt][2 * kg].x * inv0, o[mt][2 * kg].y * inv0),
          pk(o[mt][2 * kg].z * inv8, o[mt][2 * kg].w * inv8),
          pk(o[mt][2 * kg + 1].x * inv0, o[mt][2 * kg + 1].y * inv0),
          pk(o[mt][2 * kg + 1].z * inv8, o[mt][2 * kg + 1].w * inv8));
      Of4[((size_t)rtA * 16 + h * 2 + kg) * 32 + lane] = val;
    }
  }
}

// ---------------------------------------------------------------------------
// Output projection: g_Of (fp16 A-frags) @ Wo + bo. Grid 256, 128 threads
// (4 warps x mt=2 = 8 row-tiles). Deep unroll for LDG MLP; reg cap released.
// ---------------------------------------------------------------------------
#define OPROJ_SMEM (8192 * 4)

__global__ __launch_bounds__(128, 2) void oproj_kernel(
    const float* __restrict__ bo, float* __restrict__ outg) {
  extern __shared__ unsigned smo[];

  const int tid = threadIdx.x;
  {
    uint4* dst = (uint4*)smo;
#pragma unroll
    for (int i = tid; i < 2048; i += 128)
      dst[i] = ((const uint4*)g_Wofu)[i];
  }
  __syncthreads();

  const int w = tid >> 5, lane = tid & 31;
  const int r4 = lane >> 2, c4 = lane & 3;
  const int rt0 = blockIdx.x * 8 + w * 2;

  const uint2* Wo2 = (const uint2*)smo;
  const uint4* Of4 = (const uint4*)g_Of;

  float4 acc[2][8];
#pragma unroll
  for (int i = 0; i < 2; i++)
#pragma unroll
    for (int j = 0; j < 8; j++) acc[i][j] = make_float4(0.f, 0.f, 0.f, 0.f);

#pragma unroll 8
  for (int kg = 0; kg < 16; kg++) {
    uint4 A0 = Of4[((size_t)(rt0 + 0) * 16 + kg) * 32 + lane];
    uint4 A1 = Of4[((size_t)(rt0 + 1) * 16 + kg) * 32 + lane];
#pragma unroll
    for (int nf = 0; nf < 8; nf++) {
      uint2 B = Wo2[(kg * 8 + nf) * 32 + lane];
      mma16(acc[0][nf], A0.x, A0.y, A0.z, A0.w, B.x, B.y);
      mma16(acc[1][nf], A1.x, A1.y, A1.z, A1.w, B.x, B.y);
    }
  }

#pragma unroll
  for (int mt = 0; mt < 2; mt++) {
    int row = (rt0 + mt) * 16 + r4;
#pragma unroll
    for (int nf = 0; nf < 8; nf++) {
      int col = nf * 8 + 2 * c4;
      float2 bb = *(const float2*)(bo + col);
      *(float2*)(outg + (size_t)row * 64 + col) =
          make_float2(acc[mt][nf].x + bb.x, acc[mt][nf].y + bb.y);
      *(float2*)(outg + (size_t)(row + 8) * 64 + col) =
          make_float2(acc[mt][nf].z + bb.x, acc[mt][nf].w + bb.y);
    }
  }
}

// ---------------------------------------------------------------------------
extern "C" void kernel_launch(void* const* d_in, const int* in_sizes, int n_in,
                              void* d_out, int out_size) {
  const float* input_q  = (const float*)d_in[0];
  const float* input_kv = (const float*)d_in[1];
  const float* mask     = (const float*)d_in[2];
  const float* bias     = (const float*)d_in[3];
  const float* wq       = (const float*)d_in[4];
  const float* wk       = (const float*)d_in[5];
  const float* wv       = (const float*)d_in[6];
  const float* wo       = (const float*)d_in[7];
  const float* bo       = (const float*)d_in[8];
  float* out = (float*)d_out;

  cudaFuncSetAttribute(attn_kernel, cudaFuncAttributeMaxDynamicSharedMemorySize,
                       ATTN_SMEM);
  cudaFuncSetAttribute(oproj_kernel, cudaFuncAttributeMaxDynamicSharedMemorySize,
                       OPROJ_SMEM);

  prep_kernel<<<3200, 256>>>(wq, wk, wv, wo, bias, input_q, input_kv);
  attn_kernel<<<dim3(S_LEN, NH), 256, ATTN_SMEM>>>(mask);
  oproj_kernel<<<256, 128, OPROJ_SMEM>>>(bo, out);
}